// round 15
// baseline (speedup 1.0000x reference)
#include <cuda_runtime.h>

// AllZeroDigitalFilter, scalar FFMA, fully software-pipelined.
//   out[b, n*P+p] = y0 + (p/P)*y1 ; y0 = x*h0, y1 = x*(h1-h0)
// K-split x2 (two 160-thread teams x 128 taps), RR=4 outputs/thread,
// 8-tap inner iterations: 64 FFMA + 6 LDS.128 per iter; window AND coefficients
// both double-buffered -> every LDS->use distance is a full iteration.

#define TAPS 256
#define HALF 128
#define MM   255
#define PP   80
#define SEG  8
#define OUTB (SEG * PP)            // 640 outputs per block
#define RR   4
#define TEAM (OUTB / RR)           // 160 threads per team
#define NTHREADS (2 * TEAM)        // 320 threads
#define FSTRIDE (2 * TAPS + 16)    // h0[256] | d[256] | pad16 (covers dead prefetch)
#define NB 800
#define BB 8
#define TT (NB * PP)
#define NBLK (NB / SEG)            // 100

__global__ __launch_bounds__(NTHREADS)
void azdf_kernel(const float* __restrict__ x,
                 const float* __restrict__ h,
                 float* __restrict__ out)
{
    __shared__ float sf[SEG * FSTRIDE];                 // filters (h0 | d)
    __shared__ __align__(16) float sx[8 + TAPS + OUTB]; // window (8-float front pad)
    __shared__ float spart[TEAM * 20];                  // team-1 partials

    const int tid = threadIdx.x;
    const int b   = blockIdx.x / NBLK;
    const int n0  = (blockIdx.x % NBLK) * SEG;

    // ---- stage filters: h0 and d = h1-h0 per segment
    {
        const float4* hb = (const float4*)(h + (size_t)b * NB * TAPS);
        for (int idx = tid; idx < SEG * (TAPS / 4); idx += NTHREADS) {
            int s  = idx >> 6;
            int k4 = idx & 63;
            int n  = n0 + s;
            int nn = (n + 1 < NB) ? (n + 1) : (NB - 1);
            float4 a = hb[n  * (TAPS / 4) + k4];
            float4 c = hb[nn * (TAPS / 4) + k4];
            float* f0 = sf + s * FSTRIDE;
            float* f1 = f0 + TAPS;
            f0[k4 * 4 + 0] = a.x; f0[k4 * 4 + 1] = a.y;
            f0[k4 * 4 + 2] = a.z; f0[k4 * 4 + 3] = a.w;
            f1[k4 * 4 + 0] = c.x - a.x; f1[k4 * 4 + 1] = c.y - a.y;
            f1[k4 * 4 + 2] = c.z - a.z; f1[k4 * 4 + 3] = c.w - a.w;
        }
    }
    // ---- stage x window: global [n0*P - M, n0*P - M + 895], OOB -> 0
    {
        const float* xb = x + (size_t)b * TT;
        const int gbase = n0 * PP - MM;
        for (int j = tid; j < TAPS + OUTB; j += NTHREADS) {
            int g = gbase + j;
            sx[8 + j] = (g >= 0 && g < TT) ? xb[g] : 0.0f;
        }
        if (tid < 8) sx[tid] = 0.0f;
    }
    __syncthreads();

    const int lane = (tid < TEAM) ? tid : (tid - TEAM);
    const int team = (tid < TEAM) ? 0 : 1;
    const int koff = team * HALF;
    const int pout = lane * RR;
    const int s    = lane / (PP / RR);             // lane/20
    const float* f0  = sf + s * FSTRIDE + koff;
    const float* f1  = f0 + TAPS;
    const float* wb  = sx + 8 + pout - koff;

    float a00 = 0.f, a01 = 0.f, a02 = 0.f, a03 = 0.f;   // conv h0
    float a10 = 0.f, a11 = 0.f, a12 = 0.f, a13 = 0.f;   // conv d

    // Window: W[i] = wb[248 - 8*kk + i], i = 0..11; tap u, output r uses W[7-u+r]
    float W[12];
    {
        float4 t0 = *(const float4*)(wb + 248);
        float4 t1 = *(const float4*)(wb + 252);
        float4 t2 = *(const float4*)(wb + 256);
        W[0]=t0.x; W[1]=t0.y; W[2]=t0.z; W[3]=t0.w;
        W[4]=t1.x; W[5]=t1.y; W[6]=t1.z; W[7]=t1.w;
        W[8]=t2.x; W[9]=t2.y; W[10]=t2.z; W[11]=t2.w;
    }
    // current coefficients (taps 0..7)
    float4 c0a = *(const float4*)(f0);
    float4 c0b = *(const float4*)(f0 + 4);
    float4 c1a = *(const float4*)(f1);
    float4 c1b = *(const float4*)(f1 + 4);

    #pragma unroll 4
    for (int kk = 0; kk < HALF / 8; kk++) {
        // ---- prefetch EVERYTHING for iteration kk+1 (dead final reads land in pads)
        float4 nw0 = *(const float4*)(wb + 244 - 8 * kk);   // next W[4..7]
        float4 nw1 = *(const float4*)(wb + 240 - 8 * kk);   // next W[0..3]
        float4 n0a = *(const float4*)(f0 + 8 * kk + 8);
        float4 n0b = *(const float4*)(f0 + 8 * kk + 12);
        float4 n1a = *(const float4*)(f1 + 8 * kk + 8);
        float4 n1b = *(const float4*)(f1 + 8 * kk + 12);

        // ---- 64 FFMA on fully-resident operands
        a00 += W[7] * c0a.x; a01 += W[8] * c0a.x; a02 += W[9] * c0a.x; a03 += W[10] * c0a.x;
        a10 += W[7] * c1a.x; a11 += W[8] * c1a.x; a12 += W[9] * c1a.x; a13 += W[10] * c1a.x;
        a00 += W[6] * c0a.y; a01 += W[7] * c0a.y; a02 += W[8] * c0a.y; a03 += W[9]  * c0a.y;
        a10 += W[6] * c1a.y; a11 += W[7] * c1a.y; a12 += W[8] * c1a.y; a13 += W[9]  * c1a.y;
        a00 += W[5] * c0a.z; a01 += W[6] * c0a.z; a02 += W[7] * c0a.z; a03 += W[8]  * c0a.z;
        a10 += W[5] * c1a.z; a11 += W[6] * c1a.z; a12 += W[7] * c1a.z; a13 += W[8]  * c1a.z;
        a00 += W[4] * c0a.w; a01 += W[5] * c0a.w; a02 += W[6] * c0a.w; a03 += W[7]  * c0a.w;
        a10 += W[4] * c1a.w; a11 += W[5] * c1a.w; a12 += W[6] * c1a.w; a13 += W[7]  * c1a.w;
        a00 += W[3] * c0b.x; a01 += W[4] * c0b.x; a02 += W[5] * c0b.x; a03 += W[6]  * c0b.x;
        a10 += W[3] * c1b.x; a11 += W[4] * c1b.x; a12 += W[5] * c1b.x; a13 += W[6]  * c1b.x;
        a00 += W[2] * c0b.y; a01 += W[3] * c0b.y; a02 += W[4] * c0b.y; a03 += W[5]  * c0b.y;
        a10 += W[2] * c1b.y; a11 += W[3] * c1b.y; a12 += W[4] * c1b.y; a13 += W[5]  * c1b.y;
        a00 += W[1] * c0b.z; a01 += W[2] * c0b.z; a02 += W[3] * c0b.z; a03 += W[4]  * c0b.z;
        a10 += W[1] * c1b.z; a11 += W[2] * c1b.z; a12 += W[3] * c1b.z; a13 += W[4]  * c1b.z;
        a00 += W[0] * c0b.w; a01 += W[1] * c0b.w; a02 += W[2] * c0b.w; a03 += W[3]  * c0b.w;
        a10 += W[0] * c1b.w; a11 += W[1] * c1b.w; a12 += W[2] * c1b.w; a13 += W[3]  * c1b.w;

        // ---- commit prefetched operands (W[0..3] carry is register-renamed)
        W[8]  = W[0]; W[9]  = W[1]; W[10] = W[2]; W[11] = W[3];
        W[4]  = nw0.x; W[5]  = nw0.y; W[6]  = nw0.z; W[7]  = nw0.w;
        W[0]  = nw1.x; W[1]  = nw1.y; W[2]  = nw1.z; W[3]  = nw1.w;
        c0a = n0a; c0b = n0b; c1a = n1a; c1b = n1b;
    }

    if (team == 1) {
        float* sp = spart + lane * 20;
        ((float4*)sp)[0] = make_float4(a00, a01, a02, a03);
        ((float4*)sp)[1] = make_float4(a10, a11, a12, a13);
    }
    __syncthreads();
    if (team == 0) {
        const float* sp = spart + lane * 20;
        float4 p0 = ((const float4*)sp)[0];
        float4 p1 = ((const float4*)sp)[1];
        a00 += p0.x; a01 += p0.y; a02 += p0.z; a03 += p0.w;
        a10 += p1.x; a11 += p1.y; a12 += p1.z; a13 += p1.w;

        const float pb  = (float)(pout - s * PP);
        const float inv = 1.0f / (float)PP;
        float4 o;
        o.x = a00 + (pb + 0.0f) * inv * a10;
        o.y = a01 + (pb + 1.0f) * inv * a11;
        o.z = a02 + (pb + 2.0f) * inv * a12;
        o.w = a03 + (pb + 3.0f) * inv * a13;
        *(float4*)(out + (size_t)b * TT + n0 * PP + pout) = o;
    }
}

extern "C" void kernel_launch(void* const* d_in, const int* in_sizes, int n_in,
                              void* d_out, int out_size)
{
    const float* x = (const float*)d_in[0];
    const float* h = (const float*)d_in[1];
    float* out = (float*)d_out;
    (void)in_sizes; (void)n_in; (void)out_size;

    azdf_kernel<<<NBLK * BB, NTHREADS>>>(x, h, out);   // 800 blocks, 1D
}

// round 16
// speedup vs baseline: 1.0310x; 1.0310x over previous
#include <cuda_runtime.h>

// AllZeroDigitalFilter, scalar FFMA — R15 inner loop, halved block for wave balance.
//   out[b, n*P+p] = y0 + (p/P)*y1 ; y0 = x*h0, y1 = x*(h1-h0)
// SEG=4 segments/block, 160 threads (two 80-thread K-split teams x 128 taps),
// RR=4 outputs/thread, 8-tap iterations (64 FFMA + 6 LDS.128), all operands
// double-buffered. 1600 blocks -> ~8 resident blocks/SM, fine-grained balance.

#define TAPS 256
#define HALF 128
#define MM   255
#define PP   80
#define SEG  4
#define OUTB (SEG * PP)            // 320 outputs per block
#define RR   4
#define TEAM (OUTB / RR)           // 80 threads per team
#define NTHREADS (2 * TEAM)        // 160 threads
#define FSTRIDE (2 * TAPS + 16)    // h0[256] | d[256] | pad16
#define NB 800
#define BB 8
#define TT (NB * PP)
#define NBLK (NB / SEG)            // 200

__global__ __launch_bounds__(NTHREADS)
void azdf_kernel(const float* __restrict__ x,
                 const float* __restrict__ h,
                 float* __restrict__ out)
{
    __shared__ float sf[SEG * FSTRIDE];                 // 8.4 KB filters (h0 | d)
    __shared__ __align__(16) float sx[8 + TAPS + OUTB]; // 2.3 KB window (front pad)
    __shared__ float spart[TEAM * 20];                  // 6.4 KB team-1 partials

    const int tid = threadIdx.x;
    const int b   = blockIdx.x / NBLK;
    const int n0  = (blockIdx.x % NBLK) * SEG;

    // ---- stage filters: h0 and d = h1-h0 per segment
    {
        const float4* hb = (const float4*)(h + (size_t)b * NB * TAPS);
        for (int idx = tid; idx < SEG * (TAPS / 4); idx += NTHREADS) {
            int s  = idx >> 6;
            int k4 = idx & 63;
            int n  = n0 + s;
            int nn = (n + 1 < NB) ? (n + 1) : (NB - 1);
            float4 a = hb[n  * (TAPS / 4) + k4];
            float4 c = hb[nn * (TAPS / 4) + k4];
            float* f0 = sf + s * FSTRIDE;
            float* f1 = f0 + TAPS;
            f0[k4 * 4 + 0] = a.x; f0[k4 * 4 + 1] = a.y;
            f0[k4 * 4 + 2] = a.z; f0[k4 * 4 + 3] = a.w;
            f1[k4 * 4 + 0] = c.x - a.x; f1[k4 * 4 + 1] = c.y - a.y;
            f1[k4 * 4 + 2] = c.z - a.z; f1[k4 * 4 + 3] = c.w - a.w;
        }
    }
    // ---- stage x window: global [n0*P - M, n0*P - M + 575], OOB -> 0
    {
        const float* xb = x + (size_t)b * TT;
        const int gbase = n0 * PP - MM;
        for (int j = tid; j < TAPS + OUTB; j += NTHREADS) {
            int g = gbase + j;
            sx[8 + j] = (g >= 0 && g < TT) ? xb[g] : 0.0f;
        }
        if (tid < 8) sx[tid] = 0.0f;
    }
    __syncthreads();

    const int lane = (tid < TEAM) ? tid : (tid - TEAM);
    const int team = (tid < TEAM) ? 0 : 1;
    const int koff = team * HALF;
    const int pout = lane * RR;
    const int s    = lane / (PP / RR);             // lane/20
    const float* f0  = sf + s * FSTRIDE + koff;
    const float* f1  = f0 + TAPS;
    const float* wb  = sx + 8 + pout - koff;

    float a00 = 0.f, a01 = 0.f, a02 = 0.f, a03 = 0.f;   // conv h0
    float a10 = 0.f, a11 = 0.f, a12 = 0.f, a13 = 0.f;   // conv d

    // Window: W[i] = wb[248 - 8*kk + i], i = 0..11; tap u, output r uses W[7-u+r]
    float W[12];
    {
        float4 t0 = *(const float4*)(wb + 248);
        float4 t1 = *(const float4*)(wb + 252);
        float4 t2 = *(const float4*)(wb + 256);
        W[0]=t0.x; W[1]=t0.y; W[2]=t0.z; W[3]=t0.w;
        W[4]=t1.x; W[5]=t1.y; W[6]=t1.z; W[7]=t1.w;
        W[8]=t2.x; W[9]=t2.y; W[10]=t2.z; W[11]=t2.w;
    }
    // current coefficients (taps 0..7)
    float4 c0a = *(const float4*)(f0);
    float4 c0b = *(const float4*)(f0 + 4);
    float4 c1a = *(const float4*)(f1);
    float4 c1b = *(const float4*)(f1 + 4);

    #pragma unroll 4
    for (int kk = 0; kk < HALF / 8; kk++) {
        // ---- prefetch everything for iteration kk+1 (dead final reads land in pads)
        float4 nw0 = *(const float4*)(wb + 244 - 8 * kk);   // next W[4..7]
        float4 nw1 = *(const float4*)(wb + 240 - 8 * kk);   // next W[0..3]
        float4 n0a = *(const float4*)(f0 + 8 * kk + 8);
        float4 n0b = *(const float4*)(f0 + 8 * kk + 12);
        float4 n1a = *(const float4*)(f1 + 8 * kk + 8);
        float4 n1b = *(const float4*)(f1 + 8 * kk + 12);

        // ---- 64 FFMA on fully-resident operands
        a00 += W[7] * c0a.x; a01 += W[8] * c0a.x; a02 += W[9] * c0a.x; a03 += W[10] * c0a.x;
        a10 += W[7] * c1a.x; a11 += W[8] * c1a.x; a12 += W[9] * c1a.x; a13 += W[10] * c1a.x;
        a00 += W[6] * c0a.y; a01 += W[7] * c0a.y; a02 += W[8] * c0a.y; a03 += W[9]  * c0a.y;
        a10 += W[6] * c1a.y; a11 += W[7] * c1a.y; a12 += W[8] * c1a.y; a13 += W[9]  * c1a.y;
        a00 += W[5] * c0a.z; a01 += W[6] * c0a.z; a02 += W[7] * c0a.z; a03 += W[8]  * c0a.z;
        a10 += W[5] * c1a.z; a11 += W[6] * c1a.z; a12 += W[7] * c1a.z; a13 += W[8]  * c1a.z;
        a00 += W[4] * c0a.w; a01 += W[5] * c0a.w; a02 += W[6] * c0a.w; a03 += W[7]  * c0a.w;
        a10 += W[4] * c1a.w; a11 += W[5] * c1a.w; a12 += W[6] * c1a.w; a13 += W[7]  * c1a.w;
        a00 += W[3] * c0b.x; a01 += W[4] * c0b.x; a02 += W[5] * c0b.x; a03 += W[6]  * c0b.x;
        a10 += W[3] * c1b.x; a11 += W[4] * c1b.x; a12 += W[5] * c1b.x; a13 += W[6]  * c1b.x;
        a00 += W[2] * c0b.y; a01 += W[3] * c0b.y; a02 += W[4] * c0b.y; a03 += W[5]  * c0b.y;
        a10 += W[2] * c1b.y; a11 += W[3] * c1b.y; a12 += W[4] * c1b.y; a13 += W[5]  * c1b.y;
        a00 += W[1] * c0b.z; a01 += W[2] * c0b.z; a02 += W[3] * c0b.z; a03 += W[4]  * c0b.z;
        a10 += W[1] * c1b.z; a11 += W[2] * c1b.z; a12 += W[3] * c1b.z; a13 += W[4]  * c1b.z;
        a00 += W[0] * c0b.w; a01 += W[1] * c0b.w; a02 += W[2] * c0b.w; a03 += W[3]  * c0b.w;
        a10 += W[0] * c1b.w; a11 += W[1] * c1b.w; a12 += W[2] * c1b.w; a13 += W[3]  * c1b.w;

        // ---- commit prefetched operands (W[0..3] carry is register-renamed)
        W[8]  = W[0]; W[9]  = W[1]; W[10] = W[2]; W[11] = W[3];
        W[4]  = nw0.x; W[5]  = nw0.y; W[6]  = nw0.z; W[7]  = nw0.w;
        W[0]  = nw1.x; W[1]  = nw1.y; W[2]  = nw1.z; W[3]  = nw1.w;
        c0a = n0a; c0b = n0b; c1a = n1a; c1b = n1b;
    }

    if (team == 1) {
        float* sp = spart + lane * 20;
        ((float4*)sp)[0] = make_float4(a00, a01, a02, a03);
        ((float4*)sp)[1] = make_float4(a10, a11, a12, a13);
    }
    __syncthreads();
    if (team == 0) {
        const float* sp = spart + lane * 20;
        float4 p0 = ((const float4*)sp)[0];
        float4 p1 = ((const float4*)sp)[1];
        a00 += p0.x; a01 += p0.y; a02 += p0.z; a03 += p0.w;
        a10 += p1.x; a11 += p1.y; a12 += p1.z; a13 += p1.w;

        const float pb  = (float)(pout - s * PP);
        const float inv = 1.0f / (float)PP;
        float4 o;
        o.x = a00 + (pb + 0.0f) * inv * a10;
        o.y = a01 + (pb + 1.0f) * inv * a11;
        o.z = a02 + (pb + 2.0f) * inv * a12;
        o.w = a03 + (pb + 3.0f) * inv * a13;
        *(float4*)(out + (size_t)b * TT + n0 * PP + pout) = o;
    }
}

extern "C" void kernel_launch(void* const* d_in, const int* in_sizes, int n_in,
                              void* d_out, int out_size)
{
    const float* x = (const float*)d_in[0];
    const float* h = (const float*)d_in[1];
    float* out = (float*)d_out;
    (void)in_sizes; (void)n_in; (void)out_size;

    azdf_kernel<<<NBLK * BB, NTHREADS>>>(x, h, out);   // 1600 blocks, 1D
}

// round 17
// speedup vs baseline: 1.1366x; 1.1025x over previous
#include <cuda_runtime.h>

// AllZeroDigitalFilter, scalar FFMA — R16 skeleton + zero-copy filter staging.
// out[b, n*P+p] = (1-f)*conv(x, h[n]) + f*conv(x, h[n+1]),  f = p/80.
// Key change: stage SEG+1 RAW h rows (row sharing: h[n+1] of seg s == h[n] of
// seg s+1); no d = h1-h0 precompute. Teams convolve rows s and s+1 directly.
// SEG=4, 160 threads (two 80-thread K-split teams x 128 taps), RR=4,
// 8-tap iterations (64 FFMA + 8 LDS.128), all operands double-buffered.

#define TAPS 256
#define HALF 128
#define MM   255
#define PP   80
#define SEG  4
#define OUTB (SEG * PP)            // 320 outputs per block
#define RR   4
#define TEAM (OUTB / RR)           // 80 threads per team
#define NTHREADS (2 * TEAM)        // 160 threads
#define FSTRIDE (TAPS + 16)        // raw row + pad16 (covers dead prefetch)
#define NB 800
#define BB 8
#define TT (NB * PP)
#define NBLK (NB / SEG)            // 200

__global__ __launch_bounds__(NTHREADS)
void azdf_kernel(const float* __restrict__ x,
                 const float* __restrict__ h,
                 float* __restrict__ out)
{
    __shared__ float sf[(SEG + 1) * FSTRIDE];           // 5.3 KB raw h rows
    __shared__ __align__(16) float sx[8 + TAPS + OUTB]; // 2.3 KB window (front pad)
    __shared__ float spart[TEAM * 20];                  // 6.4 KB team-1 partials

    const int tid = threadIdx.x;
    const int b   = blockIdx.x / NBLK;
    const int n0  = (blockIdx.x % NBLK) * SEG;

    // ---- stage SEG+1 raw filter rows (straight float4 copy, row n0+r clamped)
    {
        const float4* hb = (const float4*)(h + (size_t)b * NB * TAPS);
        for (int idx = tid; idx < (SEG + 1) * (TAPS / 4); idx += NTHREADS) {
            int r  = idx >> 6;              // row 0..SEG
            int k4 = idx & 63;
            int n  = n0 + r;
            if (n > NB - 1) n = NB - 1;
            float4 a = hb[n * (TAPS / 4) + k4];
            *(float4*)(sf + r * FSTRIDE + k4 * 4) = a;
        }
    }
    // ---- stage x window: global [n0*P - M, n0*P - M + 575], OOB -> 0
    {
        const float* xb = x + (size_t)b * TT;
        const int gbase = n0 * PP - MM;
        for (int j = tid; j < TAPS + OUTB; j += NTHREADS) {
            int g = gbase + j;
            sx[8 + j] = (g >= 0 && g < TT) ? xb[g] : 0.0f;
        }
        if (tid < 8) sx[tid] = 0.0f;
    }
    __syncthreads();

    const int lane = (tid < TEAM) ? tid : (tid - TEAM);
    const int team = (tid < TEAM) ? 0 : 1;
    const int koff = team * HALF;
    const int pout = lane * RR;
    const int s    = lane / (PP / RR);             // lane/20
    const float* f0  = sf + s * FSTRIDE + koff;          // h[n0+s]
    const float* f1  = sf + (s + 1) * FSTRIDE + koff;    // h[n0+s+1]
    const float* wb  = sx + 8 + pout - koff;

    float a00 = 0.f, a01 = 0.f, a02 = 0.f, a03 = 0.f;   // conv h[n]
    float a10 = 0.f, a11 = 0.f, a12 = 0.f, a13 = 0.f;   // conv h[n+1]

    // Window: W[i] = wb[248 - 8*kk + i], i = 0..11; tap u, output r uses W[7-u+r]
    float W[12];
    {
        float4 t0 = *(const float4*)(wb + 248);
        float4 t1 = *(const float4*)(wb + 252);
        float4 t2 = *(const float4*)(wb + 256);
        W[0]=t0.x; W[1]=t0.y; W[2]=t0.z; W[3]=t0.w;
        W[4]=t1.x; W[5]=t1.y; W[6]=t1.z; W[7]=t1.w;
        W[8]=t2.x; W[9]=t2.y; W[10]=t2.z; W[11]=t2.w;
    }
    // current coefficients (taps 0..7 of each row)
    float4 c0a = *(const float4*)(f0);
    float4 c0b = *(const float4*)(f0 + 4);
    float4 c1a = *(const float4*)(f1);
    float4 c1b = *(const float4*)(f1 + 4);

    #pragma unroll 4
    for (int kk = 0; kk < HALF / 8; kk++) {
        // ---- prefetch everything for iteration kk+1 (dead final reads land in pads)
        float4 nw0 = *(const float4*)(wb + 244 - 8 * kk);   // next W[4..7]
        float4 nw1 = *(const float4*)(wb + 240 - 8 * kk);   // next W[0..3]
        float4 n0a = *(const float4*)(f0 + 8 * kk + 8);
        float4 n0b = *(const float4*)(f0 + 8 * kk + 12);
        float4 n1a = *(const float4*)(f1 + 8 * kk + 8);
        float4 n1b = *(const float4*)(f1 + 8 * kk + 12);

        // ---- 64 FFMA on fully-resident operands
        a00 += W[7] * c0a.x; a01 += W[8] * c0a.x; a02 += W[9] * c0a.x; a03 += W[10] * c0a.x;
        a10 += W[7] * c1a.x; a11 += W[8] * c1a.x; a12 += W[9] * c1a.x; a13 += W[10] * c1a.x;
        a00 += W[6] * c0a.y; a01 += W[7] * c0a.y; a02 += W[8] * c0a.y; a03 += W[9]  * c0a.y;
        a10 += W[6] * c1a.y; a11 += W[7] * c1a.y; a12 += W[8] * c1a.y; a13 += W[9]  * c1a.y;
        a00 += W[5] * c0a.z; a01 += W[6] * c0a.z; a02 += W[7] * c0a.z; a03 += W[8]  * c0a.z;
        a10 += W[5] * c1a.z; a11 += W[6] * c1a.z; a12 += W[7] * c1a.z; a13 += W[8]  * c1a.z;
        a00 += W[4] * c0a.w; a01 += W[5] * c0a.w; a02 += W[6] * c0a.w; a03 += W[7]  * c0a.w;
        a10 += W[4] * c1a.w; a11 += W[5] * c1a.w; a12 += W[6] * c1a.w; a13 += W[7]  * c1a.w;
        a00 += W[3] * c0b.x; a01 += W[4] * c0b.x; a02 += W[5] * c0b.x; a03 += W[6]  * c0b.x;
        a10 += W[3] * c1b.x; a11 += W[4] * c1b.x; a12 += W[5] * c1b.x; a13 += W[6]  * c1b.x;
        a00 += W[2] * c0b.y; a01 += W[3] * c0b.y; a02 += W[4] * c0b.y; a03 += W[5]  * c0b.y;
        a10 += W[2] * c1b.y; a11 += W[3] * c1b.y; a12 += W[4] * c1b.y; a13 += W[5]  * c1b.y;
        a00 += W[1] * c0b.z; a01 += W[2] * c0b.z; a02 += W[3] * c0b.z; a03 += W[4]  * c0b.z;
        a10 += W[1] * c1b.z; a11 += W[2] * c1b.z; a12 += W[3] * c1b.z; a13 += W[4]  * c1b.z;
        a00 += W[0] * c0b.w; a01 += W[1] * c0b.w; a02 += W[2] * c0b.w; a03 += W[3]  * c0b.w;
        a10 += W[0] * c1b.w; a11 += W[1] * c1b.w; a12 += W[2] * c1b.w; a13 += W[3]  * c1b.w;

        // ---- commit prefetched operands (W[0..3] carry is register-renamed)
        W[8]  = W[0]; W[9]  = W[1]; W[10] = W[2]; W[11] = W[3];
        W[4]  = nw0.x; W[5]  = nw0.y; W[6]  = nw0.z; W[7]  = nw0.w;
        W[0]  = nw1.x; W[1]  = nw1.y; W[2]  = nw1.z; W[3]  = nw1.w;
        c0a = n0a; c0b = n0b; c1a = n1a; c1b = n1b;
    }

    if (team == 1) {
        float* sp = spart + lane * 20;
        ((float4*)sp)[0] = make_float4(a00, a01, a02, a03);
        ((float4*)sp)[1] = make_float4(a10, a11, a12, a13);
    }
    __syncthreads();
    if (team == 0) {
        const float* sp = spart + lane * 20;
        float4 p0 = ((const float4*)sp)[0];
        float4 p1 = ((const float4*)sp)[1];
        a00 += p0.x; a01 += p0.y; a02 += p0.z; a03 += p0.w;
        a10 += p1.x; a11 += p1.y; a12 += p1.z; a13 += p1.w;

        // out = A0 + f * (A1 - A0),  f = p/80
        const float pb  = (float)(pout - s * PP);
        const float inv = 1.0f / (float)PP;
        float4 o;
        o.x = a00 + (pb + 0.0f) * inv * (a10 - a00);
        o.y = a01 + (pb + 1.0f) * inv * (a11 - a01);
        o.z = a02 + (pb + 2.0f) * inv * (a12 - a02);
        o.w = a03 + (pb + 3.0f) * inv * (a13 - a03);
        *(float4*)(out + (size_t)b * TT + n0 * PP + pout) = o;
    }
}

extern "C" void kernel_launch(void* const* d_in, const int* in_sizes, int n_in,
                              void* d_out, int out_size)
{
    const float* x = (const float*)d_in[0];
    const float* h = (const float*)d_in[1];
    float* out = (float*)d_out;
    (void)in_sizes; (void)n_in; (void)out_size;

    azdf_kernel<<<NBLK * BB, NTHREADS>>>(x, h, out);   // 1600 blocks, 1D
}